// round 2
// baseline (speedup 1.0000x reference)
#include <cuda_runtime.h>
#include <math.h>

#define NTOK 49
#define DIM 96
#define HEADS 3
#define HD 32
#define QKVC 288

constexpr int XS_STRIDE  = 100;  // padded row stride for x / attn-out tile
constexpr int QKV_STRIDE = 292;  // padded row stride for qkv tile
constexpr int ATT_STRIDE = 52;   // padded row stride for attention logits
constexpr int SMEM_FLOATS = NTOK * XS_STRIDE + NTOK * QKV_STRIDE + HEADS * NTOK * ATT_STRIDE;
constexpr int SMEM_BYTES  = SMEM_FLOATS * 4;   // 107,408 B -> 2 CTAs / SM

__global__ void __launch_bounds__(288, 2)
win_attn_kernel(const float* __restrict__ x,
                const float* __restrict__ qkv_w,
                const float* __restrict__ qkv_b,
                const float* __restrict__ proj_w,
                const float* __restrict__ proj_b,
                const float* __restrict__ bias_table,
                const int*   __restrict__ rel_index,
                float*       __restrict__ out)
{
    extern __shared__ float sm[];
    float* xs = sm;                              // [49][100]  x, later attn-output
    float* qs = sm + NTOK * XS_STRIDE;           // [49][292]  q|k|v per token
    float* at = qs + NTOK * QKV_STRIDE;          // [3*49][52] attention logits/probs

    const int b    = blockIdx.x;
    const int tid  = threadIdx.x;
    const int warp = tid >> 5;                   // 0..8
    const int lane = tid & 31;

    const float* xg = x + (size_t)b * (NTOK * DIM);

    // ---- stage 0: load window x into smem (float4, coalesced) ----
    for (int i = tid; i < NTOK * DIM / 4; i += 288) {
        int n  = i / (DIM / 4);
        int k4 = i % (DIM / 4);
        float4 v = ((const float4*)xg)[i];
        *(float4*)&xs[n * XS_STRIDE + 4 * k4] = v;
    }
    __syncthreads();

    // ---- stage 1: qkv = x @ qkv_w + qkv_b.  warp == 32-col slice, acc over all 49 tokens ----
    {
        const int c = (warp << 5) + lane;        // 0..287
        float acc[NTOK];
        #pragma unroll
        for (int n = 0; n < NTOK; n++) acc[n] = 0.f;
        #pragma unroll 1
        for (int k4 = 0; k4 < DIM / 4; k4++) {
            float w0 = qkv_w[(4 * k4 + 0) * QKVC + c];
            float w1 = qkv_w[(4 * k4 + 1) * QKVC + c];
            float w2 = qkv_w[(4 * k4 + 2) * QKVC + c];
            float w3 = qkv_w[(4 * k4 + 3) * QKVC + c];
            #pragma unroll
            for (int n = 0; n < NTOK; n++) {
                float4 xv = *(const float4*)&xs[n * XS_STRIDE + 4 * k4];
                acc[n] = fmaf(xv.x, w0, acc[n]);
                acc[n] = fmaf(xv.y, w1, acc[n]);
                acc[n] = fmaf(xv.z, w2, acc[n]);
                acc[n] = fmaf(xv.w, w3, acc[n]);
            }
        }
        float bb = qkv_b[c];
        #pragma unroll
        for (int n = 0; n < NTOK; n++) qs[n * QKV_STRIDE + c] = acc[n] + bb;
    }
    __syncthreads();

    // ---- stage 2: attention logits + relative-position bias ----
    const float scale = 0.17677669529663687f;   // 32^-0.5
    for (int r = warp; r < HEADS * NTOK; r += 9) {
        int h = r / NTOK, n = r % NTOK;
        const float* qrow  = &qs[n * QKV_STRIDE + h * HD];
        const float* kbase = &qs[DIM + h * HD];
        int m0 = lane;
        float a0 = 0.f;
        #pragma unroll
        for (int d4 = 0; d4 < HD / 4; d4++) {
            float4 qv = *(const float4*)&qrow[4 * d4];
            float4 kv = *(const float4*)&kbase[m0 * QKV_STRIDE + 4 * d4];
            a0 += qv.x * kv.x + qv.y * kv.y + qv.z * kv.z + qv.w * kv.w;
        }
        at[r * ATT_STRIDE + m0] = a0 * scale
            + bias_table[rel_index[n * NTOK + m0] * HEADS + h];
        int m1 = lane + 32;
        if (m1 < NTOK) {
            float a1 = 0.f;
            #pragma unroll
            for (int d4 = 0; d4 < HD / 4; d4++) {
                float4 qv = *(const float4*)&qrow[4 * d4];
                float4 kv = *(const float4*)&kbase[m1 * QKV_STRIDE + 4 * d4];
                a1 += qv.x * kv.x + qv.y * kv.y + qv.z * kv.z + qv.w * kv.w;
            }
            at[r * ATT_STRIDE + m1] = a1 * scale
                + bias_table[rel_index[n * NTOK + m1] * HEADS + h];
        }
    }
    __syncthreads();

    // ---- stage 3: row softmax (one warp per row) ----
    for (int r = warp; r < HEADS * NTOK; r += 9) {
        float v0 = at[r * ATT_STRIDE + lane];
        float v1 = (lane + 32 < NTOK) ? at[r * ATT_STRIDE + lane + 32] : -INFINITY;
        float mx = fmaxf(v0, v1);
        #pragma unroll
        for (int o = 16; o > 0; o >>= 1) mx = fmaxf(mx, __shfl_xor_sync(0xffffffffu, mx, o));
        float e0 = __expf(v0 - mx);
        float e1 = (lane + 32 < NTOK) ? __expf(v1 - mx) : 0.f;
        float s = e0 + e1;
        #pragma unroll
        for (int o = 16; o > 0; o >>= 1) s += __shfl_xor_sync(0xffffffffu, s, o);
        float inv = 1.0f / s;
        at[r * ATT_STRIDE + lane] = e0 * inv;
        if (lane + 32 < NTOK) at[r * ATT_STRIDE + lane + 32] = e1 * inv;
    }
    __syncthreads();

    // ---- stage 4: attn @ v  -> xs (reused as [49][96] head-interleaved output) ----
    {
        const int hg  = warp % 3;                // head
        const int tch = warp / 3;                // token residue class mod 3
        const int c   = hg * HD + lane;
        float acc[17];
        #pragma unroll
        for (int j = 0; j < 17; j++) acc[j] = 0.f;
        const float* vbase = &qs[2 * DIM + c];
        const float* arow  = &at[hg * NTOK * ATT_STRIDE];
        #pragma unroll 1
        for (int m = 0; m < NTOK; m++) {
            float vv = vbase[m * QKV_STRIDE];
            #pragma unroll
            for (int j = 0; j < 17; j++) {
                int n = tch + 3 * j;
                if (n < NTOK)
                    acc[j] = fmaf(arow[n * ATT_STRIDE + m], vv, acc[j]);
            }
        }
        #pragma unroll
        for (int j = 0; j < 17; j++) {
            int n = tch + 3 * j;
            if (n < NTOK) xs[n * XS_STRIDE + c] = acc[j];
        }
    }
    __syncthreads();

    // ---- stage 5: proj + bias, write out ----
    {
        const int cg  = warp % 3;
        const int tch = warp / 3;
        const int c   = cg * 32 + lane;
        float acc[17];
        #pragma unroll
        for (int j = 0; j < 17; j++) acc[j] = 0.f;
        #pragma unroll 1
        for (int k4 = 0; k4 < DIM / 4; k4++) {
            float w0 = proj_w[(4 * k4 + 0) * DIM + c];
            float w1 = proj_w[(4 * k4 + 1) * DIM + c];
            float w2 = proj_w[(4 * k4 + 2) * DIM + c];
            float w3 = proj_w[(4 * k4 + 3) * DIM + c];
            #pragma unroll
            for (int j = 0; j < 17; j++) {
                int n = tch + 3 * j;
                if (n < NTOK) {
                    float4 xv = *(const float4*)&xs[n * XS_STRIDE + 4 * k4];
                    acc[j] = fmaf(xv.x, w0, acc[j]);
                    acc[j] = fmaf(xv.y, w1, acc[j]);
                    acc[j] = fmaf(xv.z, w2, acc[j]);
                    acc[j] = fmaf(xv.w, w3, acc[j]);
                }
            }
        }
        float pb = proj_b[c];
        float* og = out + (size_t)b * (NTOK * DIM);
        #pragma unroll
        for (int j = 0; j < 17; j++) {
            int n = tch + 3 * j;
            if (n < NTOK) og[n * DIM + c] = acc[j] + pb;
        }
    }
}

extern "C" void kernel_launch(void* const* d_in, const int* in_sizes, int n_in,
                              void* d_out, int out_size)
{
    const float* x          = (const float*)d_in[0];
    // d_in[1] = q_global (unused by forward)
    const float* qkv_w      = (const float*)d_in[2];
    const float* qkv_b      = (const float*)d_in[3];
    const float* proj_w     = (const float*)d_in[4];
    const float* proj_b     = (const float*)d_in[5];
    const float* bias_table = (const float*)d_in[6];
    const int*   rel_index  = (const int*)d_in[7];
    float* out = (float*)d_out;

    int nwin = in_sizes[0] / (NTOK * DIM);

    cudaFuncSetAttribute(win_attn_kernel,
                         cudaFuncAttributeMaxDynamicSharedMemorySize, SMEM_BYTES);
    win_attn_kernel<<<nwin, 288, SMEM_BYTES>>>(x, qkv_w, qkv_b, proj_w, proj_b,
                                               bias_table, rel_index, out);
    (void)n_in; (void)out_size;
}

// round 3
// speedup vs baseline: 1.8239x; 1.8239x over previous
#include <cuda_runtime.h>
#include <math.h>

#define NTOK 49
#define DIM  96
#define QKVC 288

// ---- shared memory plan (floats) ----
// qs : [56][292]  q|k|v per token (rows 49..55 V-cols zeroed); later cols 0..95 reused for attn output
// xa : aliased region: x tile [49][100] (stages 0-1), then logits/probs [176][60] (stages 2-4)
constexpr int QS_STRIDE = 292;
constexpr int QS_ROWS   = 56;
constexpr int QS_SIZE   = QS_ROWS * QS_STRIDE;          // 16352
constexpr int AT_STRIDE = 60;                           // 60 mod 32 = 28 -> conflict-free frag loads
constexpr int AT_ROWS   = 3 * 56 + 8;                   // 176 (8 slack rows for padded m-tile reads)
constexpr int XA_SIZE   = AT_ROWS * AT_STRIDE;          // 10560 (also covers x tile reads up to row 63)
constexpr int XS_STRIDE = 100;
constexpr int SMEM_FLOATS = QS_SIZE + XA_SIZE;          // 26912
constexpr int SMEM_BYTES  = SMEM_FLOATS * 4;            // 107648 B -> 2 CTAs/SM

__device__ __forceinline__ unsigned f2tf(float f) {
    unsigned r;
    asm("cvt.rna.tf32.f32 %0, %1;" : "=r"(r) : "f"(f));
    return r;
}
__device__ __forceinline__ float tf32f(float f) { return __uint_as_float(f2tf(f)); }

__device__ __forceinline__ void mma_tf32(float& c0, float& c1, float& c2, float& c3,
                                         unsigned a0, unsigned a1, unsigned a2, unsigned a3,
                                         unsigned b0, unsigned b1) {
    asm volatile("mma.sync.aligned.m16n8k8.row.col.f32.tf32.tf32.f32 "
                 "{%0,%1,%2,%3}, {%4,%5,%6,%7}, {%8,%9}, {%0,%1,%2,%3};"
                 : "+f"(c0), "+f"(c1), "+f"(c2), "+f"(c3)
                 : "r"(a0), "r"(a1), "r"(a2), "r"(a3), "r"(b0), "r"(b1));
}

__global__ void __launch_bounds__(288, 2)
win_attn_kernel(const float* __restrict__ x,
                const float* __restrict__ qkv_w,
                const float* __restrict__ qkv_b,
                const float* __restrict__ proj_w,
                const float* __restrict__ proj_b,
                const float* __restrict__ bias_table,
                const int*   __restrict__ rel_index,
                float*       __restrict__ out)
{
    extern __shared__ float sm[];
    float* qs = sm;
    float* xa = sm + QS_SIZE;   // x tile, later attention logits/probs

    const int b    = blockIdx.x;
    const int tid  = threadIdx.x;
    const int warp = tid >> 5;            // 0..8
    const int lane = tid & 31;
    const int g    = lane >> 2;           // 0..7
    const int tg   = lane & 3;            // 0..3

    // ---- stage 0: load x (tf32-rounded) into xa; zero V pad rows ----
    const float* xg = x + (size_t)b * (NTOK * DIM);
    for (int i = tid; i < NTOK * DIM / 4; i += 288) {
        int n = i / (DIM / 4), k4 = i % (DIM / 4);
        float4 v = ((const float4*)xg)[i];
        float* d = &xa[n * XS_STRIDE + 4 * k4];
        d[0] = tf32f(v.x); d[1] = tf32f(v.y); d[2] = tf32f(v.z); d[3] = tf32f(v.w);
    }
    for (int i = tid; i < 7 * DIM; i += 288) {          // V rows 49..55 cols 192..287 = 0
        int r = 49 + i / DIM, c = 2 * DIM + i % DIM;
        qs[r * QS_STRIDE + c] = 0.f;
    }
    __syncthreads();

    // ---- stage 1: qkv = x @ qkv_w + qkv_b (tf32 mma). warp w owns cols [32w,32w+32) ----
    {
        const int ncol0 = warp * 32;
        const float sc = (warp < 3) ? 0.17677669529663687f : 1.0f;  // fold q-scale
        #pragma unroll 1
        for (int pass = 0; pass < 2; pass++) {
            const int m0 = pass * 32;                    // 2 m-tiles per pass
            float acc[2][4][4];
            #pragma unroll
            for (int mi = 0; mi < 2; mi++)
                #pragma unroll
                for (int ni = 0; ni < 4; ni++)
                    #pragma unroll
                    for (int j = 0; j < 4; j++) acc[mi][ni][j] = 0.f;

            #pragma unroll 1
            for (int k0 = 0; k0 < DIM; k0 += 8) {
                unsigned A[2][4];
                #pragma unroll
                for (int mi = 0; mi < 2; mi++) {
                    int r = m0 + mi * 16;
                    A[mi][0] = __float_as_uint(xa[(r + g)     * XS_STRIDE + k0 + tg]);
                    A[mi][1] = __float_as_uint(xa[(r + g + 8) * XS_STRIDE + k0 + tg]);
                    A[mi][2] = __float_as_uint(xa[(r + g)     * XS_STRIDE + k0 + tg + 4]);
                    A[mi][3] = __float_as_uint(xa[(r + g + 8) * XS_STRIDE + k0 + tg + 4]);
                }
                unsigned Bf[4][2];
                #pragma unroll
                for (int ni = 0; ni < 4; ni++) {
                    int c = ncol0 + ni * 8 + g;
                    Bf[ni][0] = f2tf(qkv_w[(k0 + tg)     * QKVC + c]);
                    Bf[ni][1] = f2tf(qkv_w[(k0 + tg + 4) * QKVC + c]);
                }
                #pragma unroll
                for (int mi = 0; mi < 2; mi++)
                    #pragma unroll
                    for (int ni = 0; ni < 4; ni++)
                        mma_tf32(acc[mi][ni][0], acc[mi][ni][1], acc[mi][ni][2], acc[mi][ni][3],
                                 A[mi][0], A[mi][1], A[mi][2], A[mi][3], Bf[ni][0], Bf[ni][1]);
            }
            #pragma unroll
            for (int mi = 0; mi < 2; mi++) {
                #pragma unroll
                for (int ni = 0; ni < 4; ni++) {
                    int c0 = ncol0 + ni * 8 + tg * 2;
                    float b0v = qkv_b[c0], b1v = qkv_b[c0 + 1];
                    int r = m0 + mi * 16 + g;
                    if (r < NTOK) {
                        qs[r * QS_STRIDE + c0]     = tf32f((acc[mi][ni][0] + b0v) * sc);
                        qs[r * QS_STRIDE + c0 + 1] = tf32f((acc[mi][ni][1] + b1v) * sc);
                    }
                    if (r + 8 < NTOK) {
                        qs[(r + 8) * QS_STRIDE + c0]     = tf32f((acc[mi][ni][2] + b0v) * sc);
                        qs[(r + 8) * QS_STRIDE + c0 + 1] = tf32f((acc[mi][ni][3] + b1v) * sc);
                    }
                }
            }
        }
    }
    __syncthreads();

    // ---- stage 2: logits = (q*scale) @ k^T + bias. 84 tiles (3 heads x 4 m x 7 n) ----
    {
        float* at = xa;
        #pragma unroll 1
        for (int t = warp; t < 84; t += 9) {
            int h = t / 28, rem = t % 28, mt = rem / 7, nt = rem % 7;
            int m0 = mt * 16, n0 = nt * 8;
            float c0 = 0.f, c1 = 0.f, c2 = 0.f, c3 = 0.f;
            #pragma unroll
            for (int k0 = 0; k0 < 32; k0 += 8) {
                int qc = h * 32 + k0;
                unsigned a0 = __float_as_uint(qs[(m0 + g)     * QS_STRIDE + qc + tg]);
                unsigned a1 = __float_as_uint(qs[(m0 + g + 8) * QS_STRIDE + qc + tg]);
                unsigned a2 = __float_as_uint(qs[(m0 + g)     * QS_STRIDE + qc + tg + 4]);
                unsigned a3 = __float_as_uint(qs[(m0 + g + 8) * QS_STRIDE + qc + tg + 4]);
                unsigned b0 = __float_as_uint(qs[(n0 + g) * QS_STRIDE + DIM + qc + tg]);
                unsigned b1 = __float_as_uint(qs[(n0 + g) * QS_STRIDE + DIM + qc + tg + 4]);
                mma_tf32(c0, c1, c2, c3, a0, a1, a2, a3, b0, b1);
            }
            int n_0 = n0 + tg * 2;
            #pragma unroll
            for (int e = 0; e < 4; e++) {
                int m = m0 + g + ((e >> 1) ? 8 : 0);
                int n = n_0 + (e & 1);
                float v = (e == 0) ? c0 : (e == 1) ? c1 : (e == 2) ? c2 : c3;
                if (m < NTOK && n < NTOK)
                    at[(h * 56 + m) * AT_STRIDE + n] =
                        v + bias_table[rel_index[m * NTOK + n] * 3 + h];
            }
        }
    }
    __syncthreads();

    // ---- stage 3: softmax per row; write rounded probs, zero pad cols 49..55 ----
    {
        float* at = xa;
        #pragma unroll 1
        for (int r = warp; r < 3 * NTOK; r += 9) {
            int h = r / NTOK, m = r % NTOK;
            float* row = &at[(h * 56 + m) * AT_STRIDE];
            float v0 = row[lane];
            float v1 = (lane < 17) ? row[lane + 32] : -INFINITY;
            float mx = fmaxf(v0, v1);
            #pragma unroll
            for (int o = 16; o > 0; o >>= 1) mx = fmaxf(mx, __shfl_xor_sync(0xffffffffu, mx, o));
            float e0 = __expf(v0 - mx);
            float e1 = (lane < 17) ? __expf(v1 - mx) : 0.f;
            float s = e0 + e1;
            #pragma unroll
            for (int o = 16; o > 0; o >>= 1) s += __shfl_xor_sync(0xffffffffu, s, o);
            float inv = 1.0f / s;
            row[lane] = tf32f(e0 * inv);
            if (lane < 17) row[lane + 32] = tf32f(e1 * inv);
            if (lane >= 25) row[lane + 24] = 0.f;   // cols 49..55 := 0 (contraction pad)
        }
    }
    __syncthreads();

    // ---- stage 4: O = P @ V -> qs cols 0..95. 48 tiles (3 heads x 4 m x 4 n), K padded to 56 ----
    {
        float* at = xa;
        #pragma unroll 1
        for (int t = warp; t < 48; t += 9) {
            int h = t / 16, rem = t % 16, mt = rem / 4, nt = rem % 4;
            int m0 = mt * 16, n0 = nt * 8;
            float c0 = 0.f, c1 = 0.f, c2 = 0.f, c3 = 0.f;
            #pragma unroll
            for (int k0 = 0; k0 < 56; k0 += 8) {
                unsigned a0 = __float_as_uint(at[(h * 56 + m0 + g)     * AT_STRIDE + k0 + tg]);
                unsigned a1 = __float_as_uint(at[(h * 56 + m0 + g + 8) * AT_STRIDE + k0 + tg]);
                unsigned a2 = __float_as_uint(at[(h * 56 + m0 + g)     * AT_STRIDE + k0 + tg + 4]);
                unsigned a3 = __float_as_uint(at[(h * 56 + m0 + g + 8) * AT_STRIDE + k0 + tg + 4]);
                int vc = 2 * DIM + h * 32 + n0 + g;
                unsigned b0 = __float_as_uint(qs[(k0 + tg)     * QS_STRIDE + vc]);
                unsigned b1 = __float_as_uint(qs[(k0 + tg + 4) * QS_STRIDE + vc]);
                mma_tf32(c0, c1, c2, c3, a0, a1, a2, a3, b0, b1);
            }
            int c_0 = h * 32 + n0 + tg * 2;
            int m = m0 + g;
            if (m < NTOK) {
                qs[m * QS_STRIDE + c_0]     = tf32f(c0);
                qs[m * QS_STRIDE + c_0 + 1] = tf32f(c1);
            }
            if (m + 8 < NTOK) {
                qs[(m + 8) * QS_STRIDE + c_0]     = tf32f(c2);
                qs[(m + 8) * QS_STRIDE + c_0 + 1] = tf32f(c3);
            }
        }
    }
    __syncthreads();

    // ---- stage 5: out = O @ proj_w + proj_b. 48 tiles (4 m x 12 n), K=96 ----
    {
        float* og = out + (size_t)b * (NTOK * DIM);
        #pragma unroll 1
        for (int t = warp; t < 48; t += 9) {
            int mt = t / 12, nt = t % 12;
            int m0 = mt * 16, n0 = nt * 8;
            float c0 = 0.f, c1 = 0.f, c2 = 0.f, c3 = 0.f;
            #pragma unroll
            for (int k0 = 0; k0 < DIM; k0 += 8) {
                unsigned a0 = __float_as_uint(qs[(m0 + g)     * QS_STRIDE + k0 + tg]);
                unsigned a1 = __float_as_uint(qs[(m0 + g + 8) * QS_STRIDE + k0 + tg]);
                unsigned a2 = __float_as_uint(qs[(m0 + g)     * QS_STRIDE + k0 + tg + 4]);
                unsigned a3 = __float_as_uint(qs[(m0 + g + 8) * QS_STRIDE + k0 + tg + 4]);
                unsigned b0 = f2tf(proj_w[(k0 + tg)     * DIM + n0 + g]);
                unsigned b1 = f2tf(proj_w[(k0 + tg + 4) * DIM + n0 + g]);
                mma_tf32(c0, c1, c2, c3, a0, a1, a2, a3, b0, b1);
            }
            int n_0 = n0 + tg * 2;
            float pb0 = proj_b[n_0], pb1 = proj_b[n_0 + 1];
            int m = m0 + g;
            if (m < NTOK) {
                og[m * DIM + n_0]     = c0 + pb0;
                og[m * DIM + n_0 + 1] = c1 + pb1;
            }
            if (m + 8 < NTOK) {
                og[(m + 8) * DIM + n_0]     = c2 + pb0;
                og[(m + 8) * DIM + n_0 + 1] = c3 + pb1;
            }
        }
    }
}

extern "C" void kernel_launch(void* const* d_in, const int* in_sizes, int n_in,
                              void* d_out, int out_size)
{
    const float* x          = (const float*)d_in[0];
    // d_in[1] = q_global (unused by forward)
    const float* qkv_w      = (const float*)d_in[2];
    const float* qkv_b      = (const float*)d_in[3];
    const float* proj_w     = (const float*)d_in[4];
    const float* proj_b     = (const float*)d_in[5];
    const float* bias_table = (const float*)d_in[6];
    const int*   rel_index  = (const int*)d_in[7];
    float* out = (float*)d_out;

    int nwin = in_sizes[0] / (NTOK * DIM);

    cudaFuncSetAttribute(win_attn_kernel,
                         cudaFuncAttributeMaxDynamicSharedMemorySize, SMEM_BYTES);
    win_attn_kernel<<<nwin, 288, SMEM_BYTES>>>(x, qkv_w, qkv_b, proj_w, proj_b,
                                               bias_table, rel_index, out);
    (void)n_in; (void)out_size;
}